// round 3
// baseline (speedup 1.0000x reference)
#include <cuda_runtime.h>
#include <cuda_bf16.h>
#include <cstdint>
#include <cstddef>

#define BB   64
#define TT   512
#define IND  64
#define HIDD 256

// ---------------- device scratch (static allocs are allowed) ----------------
__device__ __nv_bfloat16 g_Wt[(size_t)HIDD * HIDD * HIDD];  // [i][k][j]  33.5 MB
__device__ float         g_x[BB * HIDD];                    // current state
__device__ __nv_bfloat16 g_r[2][BB * HIDD];                 // ping-pong tanh(x) bf16

// ---------------- helpers ----------------
__device__ __forceinline__ void mma16816(float* c,
    uint32_t a0, uint32_t a1, uint32_t a2, uint32_t a3,
    uint32_t b0, uint32_t b1)
{
    asm volatile(
        "mma.sync.aligned.m16n8k16.row.col.f32.bf16.bf16.f32 "
        "{%0,%1,%2,%3},{%4,%5,%6,%7},{%8,%9},{%0,%1,%2,%3};"
        : "+f"(c[0]), "+f"(c[1]), "+f"(c[2]), "+f"(c[3])
        : "r"(a0), "r"(a1), "r"(a2), "r"(a3), "r"(b0), "r"(b1));
}

__device__ __forceinline__ void cp16(void* dst, const void* src)
{
    uint32_t d = (uint32_t)__cvta_generic_to_shared(dst);
    asm volatile("cp.async.cg.shared.global [%0], [%1], 16;\n" :: "r"(d), "l"(src) : "memory");
}
__device__ __forceinline__ void cp_commit()
{
    asm volatile("cp.async.commit_group;\n" ::: "memory");
}

// ---------------- W conversion: fp32 [i][j][k] -> bf16 [i][k][j] ----------------
__global__ void convert_kernel(const float* __restrict__ W)
{
    __shared__ __nv_bfloat16 tile[32][36];
    const int i   = blockIdx.x;
    const float*         Wi = W    + (size_t)i * HIDD * HIDD;
    __nv_bfloat16*       Oi = g_Wt + (size_t)i * HIDD * HIDD;
    const int tid = threadIdx.x;
    const int r   = tid >> 3;
    const int c4  = (tid & 7) * 4;

    for (int tt = 0; tt < 64; ++tt) {
        const int jt = tt >> 3, kt = tt & 7;
        float4 v = *(const float4*)(Wi + (size_t)(jt * 32 + r) * HIDD + kt * 32 + c4);
        tile[r][c4 + 0] = __float2bfloat16(v.x);
        tile[r][c4 + 1] = __float2bfloat16(v.y);
        tile[r][c4 + 2] = __float2bfloat16(v.z);
        tile[r][c4 + 3] = __float2bfloat16(v.w);
        __syncthreads();
        uint2 ov;
        __nv_bfloat16* op = reinterpret_cast<__nv_bfloat16*>(&ov);
        op[0] = tile[c4 + 0][r];
        op[1] = tile[c4 + 1][r];
        op[2] = tile[c4 + 2][r];
        op[3] = tile[c4 + 3][r];
        *(uint2*)(Oi + (size_t)(kt * 32 + r) * HIDD + jt * 32 + c4) = ov;
        __syncthreads();
    }
}

// ---------------- init: x = x0, r0 = tanh(x0) ----------------
__global__ void init_kernel(const float* __restrict__ x0)
{
    int idx = blockIdx.x * 256 + threadIdx.x;
    if (idx < BB * HIDD) {
        float x = x0[idx];
        g_x[idx] = x;
        g_r[0][idx] = __float2bfloat16(tanhf(x));
    }
}

// ---------------- per-timestep fused kernel ----------------
// grid: 256 CTAs (one per output neuron i), 256 threads (8 warps)
// smem layout (dynamic):
//   rs    : bf16 [64][264]         33792 B  (padded rows: conflict-free A frags)
//   ws    : 2 x 256 rows x 48 B    24576 B  (double-buffered W chunk, 16 j x 256 k)
//   us    : f32 [64][65]           16640 B  (u_t slice, padded)
//   winS  : f32 [64]                 256 B
//   hpart : f32 [8][64]             2048 B
#define RS_OFF   0
#define WS_OFF   33792
#define US_OFF   (33792 + 24576)
#define WIN_OFF  (US_OFF + 16640)
#define HP_OFF   (WIN_OFF + 256)
#define SMEM_STEP (HP_OFF + 2048)

__global__ __launch_bounds__(256, 2) void step_kernel(
    const float* __restrict__ u, const float* __restrict__ noise,
    const float* __restrict__ W_in, const float* __restrict__ b_in,
    float* __restrict__ traj, int t, int par)
{
    extern __shared__ char sm[];
    __nv_bfloat16* rs  = (__nv_bfloat16*)(sm + RS_OFF);
    char*          wsB = sm + WS_OFF;
    float*         us  = (float*)(sm + US_OFF);
    float*         winS= (float*)(sm + WIN_OFF);
    float*         hp  = (float*)(sm + HP_OFF);

    const int i    = blockIdx.x;
    const int tid  = threadIdx.x;
    const int w    = tid >> 5;
    const int lane = tid & 31;
    const int g    = lane >> 2;
    const int tq   = lane & 3;

    // ---- load r (prev rates) into padded smem ----
    {
        const uint4* src = (const uint4*)g_r[par];
        for (int c = tid; c < BB * 32; c += 256) {       // 2048 16B chunks
            int b = c >> 5, q = c & 31;
            *(uint4*)(rs + b * 264 + q * 8) = src[b * 32 + q];
        }
    }
    // ---- load u_t slice [64 b][64 c] ----
    {
        int b = tid >> 2, q = tid & 3;
        const float* up = u + ((size_t)b * TT + t) * IND + q * 16;
        #pragma unroll
        for (int s = 0; s < 4; ++s) {
            float4 v = *(const float4*)(up + s * 4);
            float* d = us + b * 65 + q * 16 + s * 4;
            d[0] = v.x; d[1] = v.y; d[2] = v.z; d[3] = v.w;
        }
    }
    if (tid < IND) winS[tid] = W_in[i * IND + tid];

    // ---- prefetch first two W chunks (16 j x 256 k each) ----
    const __nv_bfloat16* Wt = g_Wt + (size_t)i * HIDD * HIDD;
    auto stage = [&](int jc, int buf) {
        const char* src = (const char*)(Wt + (size_t)tid * HIDD + jc * 16);
        char* dst = wsB + buf * 12288 + tid * 48;
        cp16(dst, src);
        cp16(dst + 16, src + 16);
    };
    stage(0, 0); cp_commit();
    stage(1, 1); cp_commit();

    float acc[4][4][4];
    #pragma unroll
    for (int mt = 0; mt < 4; ++mt)
        #pragma unroll
        for (int nt = 0; nt < 4; ++nt)
            #pragma unroll
            for (int q = 0; q < 4; ++q) acc[mt][nt][q] = 0.f;

    __syncthreads();   // rs/us/winS visible

    // ---- mainloop: S[64 b][256 k] = R[64x256 j] * Wt[i][k][j] ----
    for (int jc = 0; jc < 16; ++jc) {
        asm volatile("cp.async.wait_group 1;\n" ::: "memory");
        __syncthreads();
        const char* wb = wsB + (jc & 1) * 12288;
        uint32_t bfr[4][2];
        #pragma unroll
        for (int nt = 0; nt < 4; ++nt) {
            int n = 32 * w + 8 * nt + g;
            const char* p = wb + n * 48 + 4 * tq;
            bfr[nt][0] = *(const uint32_t*)p;
            bfr[nt][1] = *(const uint32_t*)(p + 16);
        }
        #pragma unroll
        for (int mt = 0; mt < 4; ++mt) {
            const __nv_bfloat16* ar = rs + (16 * mt + g) * 264 + jc * 16 + 2 * tq;
            uint32_t a0 = *(const uint32_t*)ar;
            uint32_t a1 = *(const uint32_t*)(ar + 8 * 264);
            uint32_t a2 = *(const uint32_t*)(ar + 8);
            uint32_t a3 = *(const uint32_t*)(ar + 8 * 264 + 8);
            #pragma unroll
            for (int nt = 0; nt < 4; ++nt)
                mma16816(acc[mt][nt], a0, a1, a2, a3, bfr[nt][0], bfr[nt][1]);
        }
        __syncthreads();
        if (jc + 2 < 16) stage(jc + 2, jc & 1);
        cp_commit();
    }

    // ---- stage 2: h[b] = sum_k S[b][k] * r[b][k] ----
    float p0[4], p1[4];
    #pragma unroll
    for (int mt = 0; mt < 4; ++mt) { p0[mt] = 0.f; p1[mt] = 0.f; }
    #pragma unroll
    for (int mt = 0; mt < 4; ++mt) {
        #pragma unroll
        for (int nt = 0; nt < 4; ++nt) {
            int n = 32 * w + 8 * nt + 2 * tq;
            uint32_t rv0 = *(const uint32_t*)(rs + (16 * mt + g) * 264 + n);
            uint32_t rv1 = *(const uint32_t*)(rs + (16 * mt + 8 + g) * 264 + n);
            float2 f0 = __bfloat1622float2(*(__nv_bfloat162*)&rv0);
            float2 f1 = __bfloat1622float2(*(__nv_bfloat162*)&rv1);
            p0[mt] += acc[mt][nt][0] * f0.x + acc[mt][nt][1] * f0.y;
            p1[mt] += acc[mt][nt][2] * f1.x + acc[mt][nt][3] * f1.y;
        }
    }
    #pragma unroll
    for (int mt = 0; mt < 4; ++mt) {
        p0[mt] += __shfl_xor_sync(0xffffffffu, p0[mt], 1);
        p0[mt] += __shfl_xor_sync(0xffffffffu, p0[mt], 2);
        p1[mt] += __shfl_xor_sync(0xffffffffu, p1[mt], 1);
        p1[mt] += __shfl_xor_sync(0xffffffffu, p1[mt], 2);
    }
    if (tq == 0) {
        #pragma unroll
        for (int mt = 0; mt < 4; ++mt) {
            hp[w * 64 + 16 * mt + g]     = p0[mt];
            hp[w * 64 + 16 * mt + 8 + g] = p1[mt];
        }
    }
    __syncthreads();

    // ---- fused update for column i ----
    if (tid < BB) {
        const int b = tid;
        float h = 0.f;
        #pragma unroll
        for (int ww = 0; ww < 8; ++ww) h += hp[ww * 64 + b];
        float inI = b_in[i];
        #pragma unroll 16
        for (int c = 0; c < IND; ++c) inI += us[b * 65 + c] * winS[c];
        float xo = g_x[b * HIDD + i];
        float nz = noise[((size_t)t * BB + b) * HIDD + i];
        float xn = xo + 0.05f * nz + 0.2f * (-xo + h + inI);
        g_x[b * HIDD + i] = xn;
        traj[((size_t)b * TT + t) * HIDD + i] = xn;
        g_r[par ^ 1][b * HIDD + i] = __float2bfloat16(tanhf(xn));
    }
}

// ---------------- epilogue: x_final copy ----------------
__global__ void finalx_kernel(float* __restrict__ xfin)
{
    int idx = blockIdx.x * 256 + threadIdx.x;
    if (idx < BB * HIDD) xfin[idx] = g_x[idx];
}

// ---------------- epilogue: out = tanh(traj) @ W_out^T + b_out ----------------
#define SMEM_OUT (64 * 260 * 4 + 32 * 256 * 4)
__global__ __launch_bounds__(256) void outgemm_kernel(
    const float* __restrict__ trajg, const float* __restrict__ W_out,
    const float* __restrict__ b_out, float* __restrict__ out)
{
    extern __shared__ char sm[];
    float* wo = (float*)sm;            // [64][260] padded
    float* th = wo + 64 * 260;         // [32][256]
    const int tid = threadIdx.x;

    for (int idx = tid; idx < IND * HIDD; idx += 256) {
        int c = idx >> 8, ii = idx & 255;
        wo[c * 260 + ii] = W_out[idx];
    }
    const size_t r0 = (size_t)blockIdx.x * 32;
    for (int idx = tid; idx < 32 * HIDD; idx += 256) {
        int rl = idx >> 8, ii = idx & 255;
        th[idx] = tanhf(trajg[(r0 + rl) * HIDD + ii]);
    }
    __syncthreads();

    const int c  = tid & 63;
    const int rb = tid >> 6;
    const float bo = b_out[c];
    for (int rr = rb; rr < 32; rr += 4) {
        float accv = bo;
        const float4* tr = (const float4*)(th + rr * HIDD);
        const float4* wr = (const float4*)(wo + c * 260);
        #pragma unroll 8
        for (int i4 = 0; i4 < HIDD / 4; ++i4) {
            float4 a = tr[i4];
            float4 wv = wr[i4];
            accv += a.x * wv.x + a.y * wv.y + a.z * wv.z + a.w * wv.w;
        }
        out[(r0 + rr) * IND + c] = accv;
    }
}

// ---------------- launch ----------------
extern "C" void kernel_launch(void* const* d_in, const int* in_sizes, int n_in,
                              void* d_out, int out_size)
{
    const float* u     = (const float*)d_in[0];  // [B,T,IN]
    const float* x0    = (const float*)d_in[1];  // [B,HID]
    const float* noise = (const float*)d_in[2];  // [T,B,HID]
    const float* W_hh  = (const float*)d_in[3];  // [HID,HID,HID]
    const float* W_in  = (const float*)d_in[4];  // [HID,IN]
    const float* b_in  = (const float*)d_in[5];  // [HID]
    const float* W_out = (const float*)d_in[6];  // [IN,HID]
    const float* b_out = (const float*)d_in[7];  // [IN]

    float* out  = (float*)d_out;                       // [B,T,IN]  2,097,152
    float* xfin = out + (size_t)BB * TT * IND;         // [B,HID]      16,384
    float* traj = xfin + (size_t)BB * HIDD;            // [B,T,HID] 8,388,608

    cudaFuncSetAttribute(step_kernel,   cudaFuncAttributeMaxDynamicSharedMemorySize, SMEM_STEP);
    cudaFuncSetAttribute(outgemm_kernel, cudaFuncAttributeMaxDynamicSharedMemorySize, SMEM_OUT);

    convert_kernel<<<HIDD, 256>>>(W_hh);
    init_kernel<<<64, 256>>>(x0);
    for (int t = 0; t < TT; ++t)
        step_kernel<<<HIDD, 256, SMEM_STEP>>>(u, noise, W_in, b_in, traj, t, t & 1);
    finalx_kernel<<<64, 256>>>(xfin);
    outgemm_kernel<<<(BB * TT) / 32, 256, SMEM_OUT>>>(traj, W_out, b_out, out);
}

// round 4
// speedup vs baseline: 1.8861x; 1.8861x over previous
#include <cuda_runtime.h>
#include <cuda_bf16.h>
#include <cstdint>
#include <cstddef>

#define BB   64
#define TT   512
#define IND  64
#define HIDD 256

// ---------------- device scratch ----------------
__device__ __nv_bfloat16 g_Wt[(size_t)HIDD * HIDD * HIDD];  // [i][jc][k][16j] swizzled, 8KB chunks
__device__ float         g_x[BB * HIDD];
__device__ __nv_bfloat16 g_r[2][BB * HIDD];
__device__ float         g_c[(size_t)TT * BB * HIDD];       // 0.05*noise + 0.2*(u@W_in^T + b_in)

// ---------------- helpers ----------------
__device__ __forceinline__ void mma16816(float* c,
    uint32_t a0, uint32_t a1, uint32_t a2, uint32_t a3,
    uint32_t b0, uint32_t b1)
{
    asm volatile(
        "mma.sync.aligned.m16n8k16.row.col.f32.bf16.bf16.f32 "
        "{%0,%1,%2,%3},{%4,%5,%6,%7},{%8,%9},{%0,%1,%2,%3};"
        : "+f"(c[0]), "+f"(c[1]), "+f"(c[2]), "+f"(c[3])
        : "r"(a0), "r"(a1), "r"(a2), "r"(a3), "r"(b0), "r"(b1));
}

__device__ __forceinline__ void mbar_init(uint32_t a, uint32_t cnt)
{
    asm volatile("mbarrier.init.shared.b64 [%0], %1;" :: "r"(a), "r"(cnt) : "memory");
}
__device__ __forceinline__ void mbar_expect_tx(uint32_t a, uint32_t bytes)
{
    asm volatile("mbarrier.arrive.expect_tx.shared.b64 _, [%0], %1;" :: "r"(a), "r"(bytes) : "memory");
}
__device__ __forceinline__ void bulk_g2s(uint32_t dst, const void* src, uint32_t bytes, uint32_t mbar)
{
    asm volatile("cp.async.bulk.shared::cta.global.mbarrier::complete_tx::bytes [%0], [%1], %2, [%3];"
                 :: "r"(dst), "l"(src), "r"(bytes), "r"(mbar) : "memory");
}
__device__ __forceinline__ void mbar_wait(uint32_t a, uint32_t parity)
{
    asm volatile(
        "{\n\t.reg .pred P;\n"
        "WAITLP_%=:\n\t"
        "mbarrier.try_wait.parity.acquire.cta.shared::cta.b64 P, [%0], %1, 0x989680;\n\t"
        "@P bra.uni WAITDN_%=;\n\t"
        "bra.uni WAITLP_%=;\n"
        "WAITDN_%=:\n\t}"
        :: "r"(a), "r"(parity) : "memory");
}

// ---------------- W conversion: fp32 [i][j][k] -> bf16 chunked swizzled [i][jc][k][16j] ----------------
__global__ void convert_kernel(const float* __restrict__ W)
{
    __shared__ __nv_bfloat16 tile[32][36];
    const int i   = blockIdx.x;
    const float* Wi = W + (size_t)i * HIDD * HIDD;
    const int tid = threadIdx.x;
    const int r   = tid >> 3;
    const int c4  = (tid & 7) * 4;

    for (int tt = 0; tt < 64; ++tt) {
        const int jt = tt >> 3, kt = tt & 7;
        float4 v = *(const float4*)(Wi + (size_t)(jt * 32 + r) * HIDD + kt * 32 + c4);
        tile[r][c4 + 0] = __float2bfloat16(v.x);
        tile[r][c4 + 1] = __float2bfloat16(v.y);
        tile[r][c4 + 2] = __float2bfloat16(v.z);
        tile[r][c4 + 3] = __float2bfloat16(v.w);
        __syncthreads();
        // transposed values: o_x = W[i][j = jt*32+c4+x][k = kt*32+r]
        __nv_bfloat162 p0, p1;
        p0.x = tile[c4 + 0][r];  p0.y = tile[c4 + 1][r];
        p1.x = tile[c4 + 2][r];  p1.y = tile[c4 + 3][r];
        const int kk  = kt * 32 + r;
        const int j0  = jt * 32 + c4;
        const int jc  = j0 >> 4;
        const int jjw = (j0 & 15) >> 1;        // even
        const int s   = kk & 7;
        __nv_bfloat16* rowb = g_Wt + (((size_t)i * 16 + jc) * 256 + kk) * 16;
        *(__nv_bfloat162*)(rowb + ((jjw ^ s) * 2))       = p0;
        *(__nv_bfloat162*)(rowb + (((jjw ^ s) ^ 1) * 2)) = p1;
        __syncthreads();
    }
}

// ---------------- init: x = x0, r0 = tanh(x0) ----------------
__global__ void init_kernel(const float* __restrict__ x0)
{
    int idx = blockIdx.x * 256 + threadIdx.x;
    if (idx < BB * HIDD) {
        float x = x0[idx];
        g_x[idx] = x;
        g_r[0][idx] = __float2bfloat16(tanhf(x));
    }
}

// ---------------- precompute: g_c[t][b][i] = 0.05*noise + 0.2*(u_t @ W_in^T + b_in) ----------------
#define PC_SMEM (64*64*4 + 256*65*4 + 256*4)
__global__ __launch_bounds__(256, 2) void precompute_kernel(
    const float* __restrict__ u, const float* __restrict__ noise,
    const float* __restrict__ W_in, const float* __restrict__ b_in)
{
    extern __shared__ __align__(16) float psm[];
    float* uT   = psm;             // [64 c][64 b]
    float* wsm  = uT + 64 * 64;    // [256][65]
    float* binS = wsm + 256 * 65;  // [256]
    const int t   = blockIdx.x;
    const int tid = threadIdx.x;

    {
        int b = tid >> 2, c0 = (tid & 3) * 16;
        const float* up = u + ((size_t)b * TT + t) * IND + c0;
        #pragma unroll
        for (int s = 0; s < 16; s += 4) {
            float4 v = *(const float4*)(up + s);
            uT[(c0 + s + 0) * 64 + b] = v.x;
            uT[(c0 + s + 1) * 64 + b] = v.y;
            uT[(c0 + s + 2) * 64 + b] = v.z;
            uT[(c0 + s + 3) * 64 + b] = v.w;
        }
    }
    for (int idx = tid; idx < HIDD * IND; idx += 256) {
        int ii = idx >> 6, c = idx & 63;
        wsm[ii * 65 + c] = W_in[idx];
    }
    if (tid < HIDD) binS[tid] = b_in[tid];
    __syncthreads();

    const int i = tid;
    const float bin = binS[i];
    for (int cb = 0; cb < 8; ++cb) {
        float acc[8];
        #pragma unroll
        for (int q = 0; q < 8; ++q) acc[q] = 0.f;
        #pragma unroll 8
        for (int c = 0; c < 64; ++c) {
            float w = wsm[i * 65 + c];
            const float4 u0 = *(const float4*)&uT[c * 64 + cb * 8];
            const float4 u1 = *(const float4*)&uT[c * 64 + cb * 8 + 4];
            acc[0] += w * u0.x; acc[1] += w * u0.y; acc[2] += w * u0.z; acc[3] += w * u0.w;
            acc[4] += w * u1.x; acc[5] += w * u1.y; acc[6] += w * u1.z; acc[7] += w * u1.w;
        }
        #pragma unroll
        for (int q = 0; q < 8; ++q) {
            int b = cb * 8 + q;
            size_t off = ((size_t)t * BB + b) * HIDD + i;
            g_c[off] = 0.05f * noise[off] + 0.2f * (acc[q] + bin);
        }
    }
}

// ---------------- per-timestep fused kernel ----------------
// smem: rs bf16[64][264] 33792 | W stages 4x8192 | hp 8x64 f32 | mbar 4x8
#define RS_OFF    0
#define WS_OFF    33792
#define HP_OFF    (WS_OFF + 4 * 8192)      // 66560
#define MB_OFF    (HP_OFF + 2048)          // 68608
#define SMEM_STEP (MB_OFF + 64)

__global__ __launch_bounds__(256, 2) void step_kernel(
    float* __restrict__ traj, int t, int par)
{
    extern __shared__ __align__(128) char sm[];
    __nv_bfloat16* rs  = (__nv_bfloat16*)(sm + RS_OFF);
    char*          wsB = sm + WS_OFF;
    float*         hp  = (float*)(sm + HP_OFF);
    const uint32_t mb0 = (uint32_t)__cvta_generic_to_shared(sm + MB_OFF);
    const uint32_t wsS = (uint32_t)__cvta_generic_to_shared(wsB);

    const int i    = blockIdx.x;
    const int tid  = threadIdx.x;
    const int w    = tid >> 5;
    const int lane = tid & 31;
    const int g    = lane >> 2;
    const int tq   = lane & 3;

    // ---- load r (prev rates) into padded smem ----
    {
        const uint4* src = (const uint4*)g_r[par];
        #pragma unroll
        for (int rep = 0; rep < 8; ++rep) {
            int c = tid + rep * 256;
            int b = c >> 5, q = c & 31;
            *(uint4*)(rs + b * 264 + q * 8) = src[c];
        }
    }
    if (tid == 0) {
        #pragma unroll
        for (int s = 0; s < 4; ++s) mbar_init(mb0 + 8 * s, 1);
    }
    __syncthreads();   // rs + mbarrier init visible

    const char* Wt = (const char*)(g_Wt + (size_t)i * HIDD * HIDD);
    if (tid == 0) {
        #pragma unroll
        for (int s = 0; s < 4; ++s) {
            mbar_expect_tx(mb0 + 8 * s, 8192);
            bulk_g2s(wsS + s * 8192, Wt + s * 8192, 8192, mb0 + 8 * s);
        }
    }

    float acc[4][4][4];
    #pragma unroll
    for (int mt = 0; mt < 4; ++mt)
        #pragma unroll
        for (int nt = 0; nt < 4; ++nt)
            #pragma unroll
            for (int q = 0; q < 4; ++q) acc[mt][nt][q] = 0.f;

    const uint32_t sw0 = (uint32_t)((tq ^ g) << 2);

    // ---- mainloop: S[64 b][256 k] = R * W_i^T ----
    for (int jc = 0; jc < 16; ++jc) {
        const int st = jc & 3;
        mbar_wait(mb0 + 8 * st, (jc >> 2) & 1);
        const char* wb = wsB + st * 8192;
        uint32_t bfr[4][2];
        #pragma unroll
        for (int nt = 0; nt < 4; ++nt) {
            int n = 32 * w + 8 * nt + g;
            const char* p = wb + n * 32;
            bfr[nt][0] = *(const uint32_t*)(p + sw0);
            bfr[nt][1] = *(const uint32_t*)(p + (sw0 ^ 16));
        }
        #pragma unroll
        for (int mt = 0; mt < 4; ++mt) {
            const __nv_bfloat16* ar = rs + (16 * mt + g) * 264 + jc * 16 + 2 * tq;
            uint32_t a0 = *(const uint32_t*)ar;
            uint32_t a1 = *(const uint32_t*)(ar + 8 * 264);
            uint32_t a2 = *(const uint32_t*)(ar + 8);
            uint32_t a3 = *(const uint32_t*)(ar + 8 * 264 + 8);
            #pragma unroll
            for (int nt = 0; nt < 4; ++nt)
                mma16816(acc[mt][nt], a0, a1, a2, a3, bfr[nt][0], bfr[nt][1]);
        }
        __syncthreads();   // all warps done reading this stage
        if (tid == 0 && jc + 4 < 16) {
            mbar_expect_tx(mb0 + 8 * st, 8192);
            bulk_g2s(wsS + st * 8192, Wt + (size_t)(jc + 4) * 8192, 8192, mb0 + 8 * st);
        }
    }

    // ---- stage 2: h[b] = sum_k S[b][k] * r[b][k] ----
    float p0[4], p1[4];
    #pragma unroll
    for (int mt = 0; mt < 4; ++mt) { p0[mt] = 0.f; p1[mt] = 0.f; }
    #pragma unroll
    for (int mt = 0; mt < 4; ++mt) {
        #pragma unroll
        for (int nt = 0; nt < 4; ++nt) {
            int n = 32 * w + 8 * nt + 2 * tq;
            uint32_t rv0 = *(const uint32_t*)(rs + (16 * mt + g) * 264 + n);
            uint32_t rv1 = *(const uint32_t*)(rs + (16 * mt + 8 + g) * 264 + n);
            float2 f0 = __bfloat1622float2(*(__nv_bfloat162*)&rv0);
            float2 f1 = __bfloat1622float2(*(__nv_bfloat162*)&rv1);
            p0[mt] += acc[mt][nt][0] * f0.x + acc[mt][nt][1] * f0.y;
            p1[mt] += acc[mt][nt][2] * f1.x + acc[mt][nt][3] * f1.y;
        }
    }
    #pragma unroll
    for (int mt = 0; mt < 4; ++mt) {
        p0[mt] += __shfl_xor_sync(0xffffffffu, p0[mt], 1);
        p0[mt] += __shfl_xor_sync(0xffffffffu, p0[mt], 2);
        p1[mt] += __shfl_xor_sync(0xffffffffu, p1[mt], 1);
        p1[mt] += __shfl_xor_sync(0xffffffffu, p1[mt], 2);
    }
    if (tq == 0) {
        #pragma unroll
        for (int mt = 0; mt < 4; ++mt) {
            hp[w * 64 + 16 * mt + g]     = p0[mt];
            hp[w * 64 + 16 * mt + 8 + g] = p1[mt];
        }
    }
    __syncthreads();

    // ---- fused update for column i:  x <- 0.8 x + 0.2 h + c ----
    if (tid < BB) {
        const int b = tid;
        float h = 0.f;
        #pragma unroll
        for (int ww = 0; ww < 8; ++ww) h += hp[ww * 64 + b];
        float xo = g_x[b * HIDD + i];
        float cc = g_c[((size_t)t * BB + b) * HIDD + i];
        float xn = 0.8f * xo + 0.2f * h + cc;
        g_x[b * HIDD + i] = xn;
        traj[((size_t)b * TT + t) * HIDD + i] = xn;
        g_r[par ^ 1][b * HIDD + i] = __float2bfloat16(tanhf(xn));
    }
}

// ---------------- epilogue: x_final copy ----------------
__global__ void finalx_kernel(float* __restrict__ xfin)
{
    int idx = blockIdx.x * 256 + threadIdx.x;
    if (idx < BB * HIDD) xfin[idx] = g_x[idx];
}

// ---------------- epilogue: out = tanh(traj) @ W_out^T + b_out ----------------
#define SMEM_OUT (64 * 260 * 4 + 32 * 256 * 4)
__global__ __launch_bounds__(256) void outgemm_kernel(
    const float* __restrict__ trajg, const float* __restrict__ W_out,
    const float* __restrict__ b_out, float* __restrict__ out)
{
    extern __shared__ char smo[];
    float* wo = (float*)smo;           // [64][260] padded
    float* th = wo + 64 * 260;         // [32][256]
    const int tid = threadIdx.x;

    for (int idx = tid; idx < IND * HIDD; idx += 256) {
        int c = idx >> 8, ii = idx & 255;
        wo[c * 260 + ii] = W_out[idx];
    }
    const size_t r0 = (size_t)blockIdx.x * 32;
    for (int idx = tid; idx < 32 * HIDD; idx += 256) {
        int rl = idx >> 8, ii = idx & 255;
        th[idx] = tanhf(trajg[(r0 + rl) * HIDD + ii]);
    }
    __syncthreads();

    const int c  = tid & 63;
    const int rb = tid >> 6;
    const float bo = b_out[c];
    for (int rr = rb; rr < 32; rr += 4) {
        float accv = bo;
        const float4* tr = (const float4*)(th + rr * HIDD);
        const float4* wr = (const float4*)(wo + c * 260);
        #pragma unroll 8
        for (int i4 = 0; i4 < HIDD / 4; ++i4) {
            float4 a  = tr[i4];
            float4 wv = wr[i4];
            accv += a.x * wv.x + a.y * wv.y + a.z * wv.z + a.w * wv.w;
        }
        out[(r0 + rr) * IND + c] = accv;
    }
}

// ---------------- launch ----------------
extern "C" void kernel_launch(void* const* d_in, const int* in_sizes, int n_in,
                              void* d_out, int out_size)
{
    const float* u     = (const float*)d_in[0];  // [B,T,IN]
    const float* x0    = (const float*)d_in[1];  // [B,HID]
    const float* noise = (const float*)d_in[2];  // [T,B,HID]
    const float* W_hh  = (const float*)d_in[3];  // [HID,HID,HID]
    const float* W_in  = (const float*)d_in[4];  // [HID,IN]
    const float* b_in  = (const float*)d_in[5];  // [HID]
    const float* W_out = (const float*)d_in[6];  // [IN,HID]
    const float* b_out = (const float*)d_in[7];  // [IN]

    float* out  = (float*)d_out;                       // [B,T,IN]
    float* xfin = out + (size_t)BB * TT * IND;         // [B,HID]
    float* traj = xfin + (size_t)BB * HIDD;            // [B,T,HID]

    cudaFuncSetAttribute(step_kernel,       cudaFuncAttributeMaxDynamicSharedMemorySize, SMEM_STEP);
    cudaFuncSetAttribute(precompute_kernel, cudaFuncAttributeMaxDynamicSharedMemorySize, PC_SMEM);
    cudaFuncSetAttribute(outgemm_kernel,    cudaFuncAttributeMaxDynamicSharedMemorySize, SMEM_OUT);

    convert_kernel<<<HIDD, 256>>>(W_hh);
    init_kernel<<<64, 256>>>(x0);
    precompute_kernel<<<TT, 256, PC_SMEM>>>(u, noise, W_in, b_in);
    for (int t = 0; t < TT; ++t)
        step_kernel<<<HIDD, 256, SMEM_STEP>>>(traj, t, t & 1);
    finalx_kernel<<<64, 256>>>(xfin);
    outgemm_kernel<<<(BB * TT) / 32, 256, SMEM_OUT>>>(traj, W_out, b_out, out);
}

// round 5
// speedup vs baseline: 2.0502x; 1.0870x over previous
#include <cuda_runtime.h>
#include <cuda_bf16.h>
#include <cstdint>
#include <cstddef>

#define BB   64
#define TT   512
#define IND  64
#define HIDD 256

// ---------------- device scratch ----------------
// W layout: [i][w 8][jc 16][k32][j16], per-(i,w) 8192 bf16 = 16KB contiguous.
// Within a 1KB jc-block: row kl (k&31) holds 16 j values; j-pair q stored at
// word q ^ (4*((kl>>2)&1))  (conflict-free for both mma B-fragment loads).
__device__ __nv_bfloat16 g_Wt[(size_t)HIDD * HIDD * HIDD];
__device__ float         g_x[BB * HIDD];
__device__ __nv_bfloat16 g_r[2][BB * HIDD];
__device__ float         g_c[(size_t)TT * BB * HIDD];  // 0.05*noise + 0.2*(u@W_in^T+b_in)

// ---------------- helpers ----------------
__device__ __forceinline__ void mma16816(float* c,
    uint32_t a0, uint32_t a1, uint32_t a2, uint32_t a3,
    uint32_t b0, uint32_t b1)
{
    asm volatile(
        "mma.sync.aligned.m16n8k16.row.col.f32.bf16.bf16.f32 "
        "{%0,%1,%2,%3},{%4,%5,%6,%7},{%8,%9},{%0,%1,%2,%3};"
        : "+f"(c[0]), "+f"(c[1]), "+f"(c[2]), "+f"(c[3])
        : "r"(a0), "r"(a1), "r"(a2), "r"(a3), "r"(b0), "r"(b1));
}
__device__ __forceinline__ void mbar_init(uint32_t a, uint32_t cnt)
{
    asm volatile("mbarrier.init.shared.b64 [%0], %1;" :: "r"(a), "r"(cnt) : "memory");
}
__device__ __forceinline__ void mbar_expect_tx(uint32_t a, uint32_t bytes)
{
    asm volatile("mbarrier.arrive.expect_tx.shared.b64 _, [%0], %1;" :: "r"(a), "r"(bytes) : "memory");
}
__device__ __forceinline__ void bulk_g2s(uint32_t dst, const void* src, uint32_t bytes, uint32_t mbar)
{
    asm volatile("cp.async.bulk.shared::cta.global.mbarrier::complete_tx::bytes [%0], [%1], %2, [%3];"
                 :: "r"(dst), "l"(src), "r"(bytes), "r"(mbar) : "memory");
}
__device__ __forceinline__ void mbar_wait(uint32_t a, uint32_t parity)
{
    asm volatile(
        "{\n\t.reg .pred P;\n"
        "WAITLP_%=:\n\t"
        "mbarrier.try_wait.parity.acquire.cta.shared::cta.b64 P, [%0], %1, 0x989680;\n\t"
        "@P bra.uni WAITDN_%=;\n\t"
        "bra.uni WAITLP_%=;\n"
        "WAITDN_%=:\n\t}"
        :: "r"(a), "r"(parity) : "memory");
}
__device__ __forceinline__ void fence_proxy_async_shared()
{
    asm volatile("fence.proxy.async.shared::cta;" ::: "memory");
}

// ---------------- W conversion: fp32 [i][j][k] -> per-warp chunked bf16 ----------------
__global__ void convert_kernel(const float* __restrict__ W)
{
    __shared__ __nv_bfloat16 tile[32][36];
    const int i   = blockIdx.x;
    const float* Wi = W + (size_t)i * HIDD * HIDD;
    const int tid = threadIdx.x;
    const int r   = tid >> 3;
    const int c4  = (tid & 7) * 4;

    for (int tt = 0; tt < 64; ++tt) {
        const int jt = tt >> 3, kt = tt & 7;
        float4 v = *(const float4*)(Wi + (size_t)(jt * 32 + r) * HIDD + kt * 32 + c4);
        tile[r][c4 + 0] = __float2bfloat16(v.x);
        tile[r][c4 + 1] = __float2bfloat16(v.y);
        tile[r][c4 + 2] = __float2bfloat16(v.z);
        tile[r][c4 + 3] = __float2bfloat16(v.w);
        __syncthreads();
        // transposed: ov holds W[i][j0..j0+3][kk]
        uint2 ov;
        __nv_bfloat16* op = reinterpret_cast<__nv_bfloat16*>(&ov);
        op[0] = tile[c4 + 0][r];
        op[1] = tile[c4 + 1][r];
        op[2] = tile[c4 + 2][r];
        op[3] = tile[c4 + 3][r];
        const int kk  = kt * 32 + r;          // 0..255
        const int j0  = jt * 32 + c4;         // 0..255 (mult of 4)
        const int wI  = kk >> 5, kl = kk & 31;
        const int jc  = j0 >> 4;
        const int q0  = (j0 & 15) >> 1;       // even
        const int bet = (kl >> 2) & 1;
        const int w0  = q0 ^ (bet << 2);      // even
        __nv_bfloat16* dst = g_Wt + (((size_t)i * 8 + wI) * 8192 + jc * 512 + kl * 16 + w0 * 2);
        *(uint2*)dst = ov;
        __syncthreads();
    }
}

// ---------------- init: x = x0, r0 = tanh(x0) ----------------
__global__ void init_kernel(const float* __restrict__ x0)
{
    int idx = blockIdx.x * 256 + threadIdx.x;
    if (idx < BB * HIDD) {
        float x = x0[idx];
        g_x[idx] = x;
        g_r[0][idx] = __float2bfloat16(tanhf(x));
    }
}

// ---------------- precompute: g_c[t][b][i] = 0.05*noise + 0.2*(u_t @ W_in^T + b_in) ----------------
#define PC_SMEM (64*64*4 + 256*65*4 + 256*4)
__global__ __launch_bounds__(256, 2) void precompute_kernel(
    const float* __restrict__ u, const float* __restrict__ noise,
    const float* __restrict__ W_in, const float* __restrict__ b_in)
{
    extern __shared__ __align__(16) float psm[];
    float* uT   = psm;             // [64 c][64 b]
    float* wsm  = uT + 64 * 64;    // [256][65]
    float* binS = wsm + 256 * 65;  // [256]
    const int t   = blockIdx.x;
    const int tid = threadIdx.x;

    {
        int b = tid >> 2, c0 = (tid & 3) * 16;
        const float* up = u + ((size_t)b * TT + t) * IND + c0;
        #pragma unroll
        for (int s = 0; s < 16; s += 4) {
            float4 v = *(const float4*)(up + s);
            uT[(c0 + s + 0) * 64 + b] = v.x;
            uT[(c0 + s + 1) * 64 + b] = v.y;
            uT[(c0 + s + 2) * 64 + b] = v.z;
            uT[(c0 + s + 3) * 64 + b] = v.w;
        }
    }
    for (int idx = tid; idx < HIDD * IND; idx += 256) {
        int ii = idx >> 6, c = idx & 63;
        wsm[ii * 65 + c] = W_in[idx];
    }
    if (tid < HIDD) binS[tid] = b_in[tid];
    __syncthreads();

    const int i = tid;
    const float bin = binS[i];
    for (int cb = 0; cb < 8; ++cb) {
        float acc[8];
        #pragma unroll
        for (int q = 0; q < 8; ++q) acc[q] = 0.f;
        #pragma unroll 8
        for (int c = 0; c < 64; ++c) {
            float w = wsm[i * 65 + c];
            const float4 u0 = *(const float4*)&uT[c * 64 + cb * 8];
            const float4 u1 = *(const float4*)&uT[c * 64 + cb * 8 + 4];
            acc[0] += w * u0.x; acc[1] += w * u0.y; acc[2] += w * u0.z; acc[3] += w * u0.w;
            acc[4] += w * u1.x; acc[5] += w * u1.y; acc[6] += w * u1.z; acc[7] += w * u1.w;
        }
        #pragma unroll
        for (int q = 0; q < 8; ++q) {
            int b = cb * 8 + q;
            size_t off = ((size_t)t * BB + b) * HIDD + i;
            g_c[off] = 0.05f * noise[off] + 0.2f * (acc[q] + bin);
        }
    }
}

// ---------------- per-timestep fused kernel ----------------
// smem: rs bf16[64][264] 33792 | per-warp rings 8 x (4 x 2048) = 65536 | hp 2048 | mbars 256
#define RS_OFF    0
#define WS_OFF    33792
#define HP_OFF    (WS_OFF + 8 * 8192)      // 99328
#define MB_OFF    (HP_OFF + 2048)          // 101376
#define SMEM_STEP (MB_OFF + 256)           // 101632

__global__ __launch_bounds__(256, 2) void step_kernel(
    float* __restrict__ traj, int t, int par)
{
    extern __shared__ __align__(128) char sm[];
    __nv_bfloat16* rs  = (__nv_bfloat16*)(sm + RS_OFF);
    char*          wsB = sm + WS_OFF;
    float*         hp  = (float*)(sm + HP_OFF);

    const int i    = blockIdx.x;
    const int tid  = threadIdx.x;
    const int w    = tid >> 5;
    const int lane = tid & 31;
    const int g    = lane >> 2;
    const int tq   = lane & 3;

    char* const    wsWp = wsB + w * 8192;                               // this warp's ring
    const uint32_t wsW  = (uint32_t)__cvta_generic_to_shared(wsWp);
    const uint32_t mb   = (uint32_t)__cvta_generic_to_shared(sm + MB_OFF) + w * 32;
    const char*    WtW  = (const char*)(g_Wt + ((size_t)i * 8 + w) * 8192);

    // ---- per-warp TMA ring: init + prefetch all 4 stages (no cross-warp sync needed) ----
    if (lane == 0) {
        #pragma unroll
        for (int st = 0; st < 4; ++st) mbar_init(mb + 8 * st, 1);
        fence_proxy_async_shared();
        #pragma unroll
        for (int st = 0; st < 4; ++st) {
            mbar_expect_tx(mb + 8 * st, 2048);
            bulk_g2s(wsW + st * 2048, WtW + st * 2048, 2048, mb + 8 * st);
        }
    }

    // ---- load r (prev rates) into padded smem ----
    {
        const uint4* src = (const uint4*)g_r[par];
        #pragma unroll
        for (int rep = 0; rep < 8; ++rep) {
            int c = tid + rep * 256;
            int b = c >> 5, q = c & 31;
            *(uint4*)(rs + b * 264 + q * 8) = src[c];
        }
    }
    __syncthreads();   // rs visible to all warps

    // per-lane constants
    const uint32_t sw0b = (uint32_t)((tq * 4) ^ (((g >> 2) & 1) << 4));
    uint32_t aAddr[4];
    {
        const int tt2   = lane >> 3, rr = lane & 7;
        const int m_off = ((tt2 & 1) << 3) + rr;
        const int c_off = (tt2 >> 1) << 3;
        const uint32_t rsS = (uint32_t)__cvta_generic_to_shared(rs);
        #pragma unroll
        for (int mt = 0; mt < 4; ++mt)
            aAddr[mt] = rsS + (uint32_t)(((16 * mt + m_off) * 264 + c_off) * 2);
    }

    float acc[4][4][4];
    #pragma unroll
    for (int mt = 0; mt < 4; ++mt)
        #pragma unroll
        for (int nt = 0; nt < 4; ++nt)
            #pragma unroll
            for (int q = 0; q < 4; ++q) acc[mt][nt][q] = 0.f;

    // ---- mainloop: fully warp-local, no block syncs ----
    for (int ch = 0; ch < 8; ++ch) {
        const int st = ch & 3;
        mbar_wait(mb + 8 * st, (ch >> 2) & 1);
        #pragma unroll
        for (int sub = 0; sub < 2; ++sub) {
            const int jc = ch * 2 + sub;
            const char* wchunk = wsWp + st * 2048 + sub * 1024;
            uint32_t bfr[4][2];
            #pragma unroll
            for (int nt = 0; nt < 4; ++nt) {
                const char* p = wchunk + (8 * nt + g) * 32;
                bfr[nt][0] = *(const uint32_t*)(p + sw0b);
                bfr[nt][1] = *(const uint32_t*)(p + (sw0b ^ 16));
            }
            #pragma unroll
            for (int mt = 0; mt < 4; ++mt) {
                uint32_t A0, A1, A2, A3;
                asm volatile("ldmatrix.sync.aligned.m8n8.x4.shared.b16 {%0,%1,%2,%3},[%4];"
                    : "=r"(A0), "=r"(A1), "=r"(A2), "=r"(A3)
                    : "r"(aAddr[mt] + (uint32_t)(jc * 32)));
                #pragma unroll
                for (int nt = 0; nt < 4; ++nt)
                    mma16816(acc[mt][nt], A0, A1, A2, A3, bfr[nt][0], bfr[nt][1]);
            }
        }
        // reissue this stage for chunk ch+4 (warp-local; LDS data already returned)
        if (lane == 0 && ch + 4 < 8) {
            mbar_expect_tx(mb + 8 * st, 2048);
            bulk_g2s(wsW + st * 2048, WtW + (size_t)(ch + 4) * 2048, 2048, mb + 8 * st);
        }
    }

    // ---- stage 2: h[b] = sum_k S[b][k] * r[b][k]  (warp-local) ----
    float p0[4], p1[4];
    #pragma unroll
    for (int mt = 0; mt < 4; ++mt) { p0[mt] = 0.f; p1[mt] = 0.f; }
    #pragma unroll
    for (int mt = 0; mt < 4; ++mt) {
        #pragma unroll
        for (int nt = 0; nt < 4; ++nt) {
            int n = 32 * w + 8 * nt + 2 * tq;
            uint32_t rv0 = *(const uint32_t*)(rs + (16 * mt + g) * 264 + n);
            uint32_t rv1 = *(const uint32_t*)(rs + (16 * mt + 8 + g) * 264 + n);
            float2 f0 = __bfloat1622float2(*(__nv_bfloat162*)&rv0);
            float2 f1 = __bfloat1622float2(*(__nv_bfloat162*)&rv1);
            p0[mt] += acc[mt][nt][0] * f0.x + acc[mt][nt][1] * f0.y;
            p1[mt] += acc[mt][nt][2] * f1.x + acc[mt][nt][3] * f1.y;
        }
    }
    #pragma unroll
    for (int mt = 0; mt < 4; ++mt) {
        p0[mt] += __shfl_xor_sync(0xffffffffu, p0[mt], 1);
        p0[mt] += __shfl_xor_sync(0xffffffffu, p0[mt], 2);
        p1[mt] += __shfl_xor_sync(0xffffffffu, p1[mt], 1);
        p1[mt] += __shfl_xor_sync(0xffffffffu, p1[mt], 2);
    }
    if (tq == 0) {
        #pragma unroll
        for (int mt = 0; mt < 4; ++mt) {
            hp[w * 64 + 16 * mt + g]     = p0[mt];
            hp[w * 64 + 16 * mt + 8 + g] = p1[mt];
        }
    }
    __syncthreads();

    // ---- fused update for column i:  x <- 0.8 x + 0.2 h + c ----
    if (tid < BB) {
        const int b = tid;
        float h = 0.f;
        #pragma unroll
        for (int ww = 0; ww < 8; ++ww) h += hp[ww * 64 + b];
        float xo = g_x[b * HIDD + i];
        float cc = g_c[((size_t)t * BB + b) * HIDD + i];
        float xn = 0.8f * xo + 0.2f * h + cc;
        g_x[b * HIDD + i] = xn;
        traj[((size_t)b * TT + t) * HIDD + i] = xn;
        g_r[par ^ 1][b * HIDD + i] = __float2bfloat16(tanhf(xn));
    }
}

// ---------------- epilogue: x_final copy ----------------
__global__ void finalx_kernel(float* __restrict__ xfin)
{
    int idx = blockIdx.x * 256 + threadIdx.x;
    if (idx < BB * HIDD) xfin[idx] = g_x[idx];
}

// ---------------- epilogue: out = tanh(traj) @ W_out^T + b_out ----------------
#define SMEM_OUT (64 * 260 * 4 + 32 * 256 * 4)
__global__ __launch_bounds__(256) void outgemm_kernel(
    const float* __restrict__ trajg, const float* __restrict__ W_out,
    const float* __restrict__ b_out, float* __restrict__ out)
{
    extern __shared__ char smo[];
    float* wo = (float*)smo;           // [64][260] padded
    float* th = wo + 64 * 260;         // [32][256]
    const int tid = threadIdx.x;

    for (int idx = tid; idx < IND * HIDD; idx += 256) {
        int c = idx >> 8, ii = idx & 255;
        wo[c * 260 + ii] = W_out[idx];
    }
    const size_t r0 = (size_t)blockIdx.x * 32;
    for (int idx = tid; idx < 32 * HIDD; idx += 256) {
        th[idx] = tanhf(trajg[r0 * HIDD + idx]);
    }
    __syncthreads();

    const int c  = tid & 63;
    const int rb = tid >> 6;
    const float bo = b_out[c];
    for (int rr = rb; rr < 32; rr += 4) {
        float accv = bo;
        const float4* tr = (const float4*)(th + rr * HIDD);
        const float4* wr = (const float4*)(wo + c * 260);
        #pragma unroll 8
        for (int i4 = 0; i4 < HIDD / 4; ++i4) {
            float4 a  = tr[i4];
            float4 wv = wr[i4];
            accv += a.x * wv.x + a.y * wv.y + a.z * wv.z + a.w * wv.w;
        }
        out[(r0 + rr) * IND + c] = accv;
    }
}

// ---------------- launch ----------------
extern "C" void kernel_launch(void* const* d_in, const int* in_sizes, int n_in,
                              void* d_out, int out_size)
{
    const float* u     = (const float*)d_in[0];  // [B,T,IN]
    const float* x0    = (const float*)d_in[1];  // [B,HID]
    const float* noise = (const float*)d_in[2];  // [T,B,HID]
    const float* W_hh  = (const float*)d_in[3];  // [HID,HID,HID]
    const float* W_in  = (const float*)d_in[4];  // [HID,IN]
    const float* b_in  = (const float*)d_in[5];  // [HID]
    const float* W_out = (const float*)d_in[6];  // [IN,HID]
    const float* b_out = (const float*)d_in[7];  // [IN]

    float* out  = (float*)d_out;                       // [B,T,IN]
    float* xfin = out + (size_t)BB * TT * IND;         // [B,HID]
    float* traj = xfin + (size_t)BB * HIDD;            // [B,T,HID]

    cudaFuncSetAttribute(step_kernel,       cudaFuncAttributeMaxDynamicSharedMemorySize, SMEM_STEP);
    cudaFuncSetAttribute(precompute_kernel, cudaFuncAttributeMaxDynamicSharedMemorySize, PC_SMEM);
    cudaFuncSetAttribute(outgemm_kernel,    cudaFuncAttributeMaxDynamicSharedMemorySize, SMEM_OUT);

    convert_kernel<<<HIDD, 256>>>(W_hh);
    init_kernel<<<64, 256>>>(x0);
    precompute_kernel<<<TT, 256, PC_SMEM>>>(u, noise, W_in, b_in);
    for (int t = 0; t < TT; ++t)
        step_kernel<<<HIDD, 256, SMEM_STEP>>>(traj, t, t & 1);
    finalx_kernel<<<64, 256>>>(xfin);
    outgemm_kernel<<<(BB * TT) / 32, 256, SMEM_OUT>>>(traj, W_out, b_out, out);
}